// round 12
// baseline (speedup 1.0000x reference)
#include <cuda_runtime.h>

typedef unsigned long long ull;

// ---------------- problem constants ------------------------------------------
#define MAX_N 100000
#define MAX_E 1600000
#define MAXDEG 128           // Poisson(16): P(deg>127) ~ 0; guarded anyway
#define LOG2_MAXDEG 7

// ---------------- device scratch (allocation-free; static zero-init) ----------
__device__ int   g_cur[MAX_N];                 // bucket cursor == degree after pass
__device__ float g_dis[MAX_N];                 // (deg+1)^{-1/2}
__device__ int   g_eslot[MAX_N * MAXDEG];      // fixed-stride CSR: src ids
__device__ __align__(16) float g_bufA[MAX_N * 96];
__device__ __align__(16) float g_bufB[MAX_N * 96];
__device__ __align__(16) float g_bufH[MAX_N * 96];

// ---------------- packed f32x2 helpers ----------------------------------------
__device__ __forceinline__ ull dup2(float x) {
    ull r;
    asm("mov.b64 %0, {%1, %1};" : "=l"(r) : "r"(__float_as_uint(x)));
    return r;
}
__device__ __forceinline__ ull fma2(ull a, ull b, ull c) {
    ull d;
    asm("fma.rn.f32x2 %0, %1, %2, %3;" : "=l"(d) : "l"(a), "l"(b), "l"(c));
    return d;
}

// ---------------- single-pass bucket+count ------------------------------------
// edge_index is INT32 (JAX x64 disabled). g_cur must be zero on entry
// (static init on call 1; k_zero_tail re-zeroes at the end of every call).
__global__ void k_bucketcount(const int* __restrict__ ei, int e, int n) {
    int i = blockIdx.x * blockDim.x + threadIdx.x;
    if (i >= e) return;
    int s = ei[i];
    int d = ei[e + i];
    if ((unsigned)s >= (unsigned)n) s = 0;   // surface as rel_err, never trap
    if ((unsigned)d >= (unsigned)n) d = 0;
    int pos = atomicAdd(&g_cur[d], 1);
    if (pos < MAXDEG) g_eslot[(d << LOG2_MAXDEG) + pos] = s;
}

__global__ void k_dis(int n) {
    int i = blockIdx.x * blockDim.x + threadIdx.x;
    if (i < n) g_dis[i] = rsqrtf((float)g_cur[i] + 1.0f);
}

__global__ void k_zero_tail(int n) {
    int i = blockIdx.x * blockDim.x + threadIdx.x;
    if (i < n) g_cur[i] = 0;
}

// ---------------- gather aggregation: out[v] = sum + h[v]*dis^2 (+bias) -------
template <int F, bool BIAS>
__global__ void __launch_bounds__(256)
k_agg(const float* __restrict__ h, const float* __restrict__ bias,
      float* __restrict__ out, int n) {
    constexpr int G = F / 4;
    int tid = blockIdx.x * blockDim.x + threadIdx.x;
    int node = tid / G;
    int v = tid - node * G;
    if (node >= n) return;

    float dn = g_dis[node];
    float d2 = dn * dn;
    float4 acc = *reinterpret_cast<const float4*>(h + (size_t)node * F + (v << 2));
    acc.x *= d2; acc.y *= d2; acc.z *= d2; acc.w *= d2;
    if (BIAS) {
        float4 bv = *reinterpret_cast<const float4*>(bias + (v << 2));
        acc.x += bv.x; acc.y += bv.y; acc.z += bv.z; acc.w += bv.w;
    }

    int deg = g_cur[node];
    if (deg > MAXDEG) deg = MAXDEG;
    const int* slots = g_eslot + ((size_t)node << LOG2_MAXDEG);

    int j = 0;
    for (; j + 4 <= deg; j += 4) {
        int4 s4 = *reinterpret_cast<const int4*>(slots + j);   // 16B-aligned
        float w0 = g_dis[s4.x] * dn;
        float w1 = g_dis[s4.y] * dn;
        float w2 = g_dis[s4.z] * dn;
        float w3 = g_dis[s4.w] * dn;
        float4 a0 = *reinterpret_cast<const float4*>(h + (size_t)s4.x * F + (v << 2));
        float4 a1 = *reinterpret_cast<const float4*>(h + (size_t)s4.y * F + (v << 2));
        float4 a2 = *reinterpret_cast<const float4*>(h + (size_t)s4.z * F + (v << 2));
        float4 a3 = *reinterpret_cast<const float4*>(h + (size_t)s4.w * F + (v << 2));
        acc.x += a0.x * w0; acc.y += a0.y * w0; acc.z += a0.z * w0; acc.w += a0.w * w0;
        acc.x += a1.x * w1; acc.y += a1.y * w1; acc.z += a1.z * w1; acc.w += a1.w * w1;
        acc.x += a2.x * w2; acc.y += a2.y * w2; acc.z += a2.z * w2; acc.w += a2.w * w2;
        acc.x += a3.x * w3; acc.y += a3.y * w3; acc.z += a3.z * w3; acc.w += a3.w * w3;
    }
    for (; j < deg; j++) {
        int s = slots[j];
        float w = g_dis[s] * dn;
        float4 a = *reinterpret_cast<const float4*>(h + (size_t)s * F + (v << 2));
        acc.x += a.x * w; acc.y += a.y * w; acc.z += a.z * w; acc.w += a.w * w;
    }
    *reinterpret_cast<float4*>(out + (size_t)node * F + (v << 2)) = acc;
}

// ---------------- GEMM: out = act(in) @ W (+bh), dup-packed f32x2 --------------
// 64-node tile, 256 threads = 8 col-groups x 32 lanes; NR=2 nodes per thread
// (lane, lane+32) x CH=FOUT/8 columns. X stored PRE-DUPLICATED in smem as ull
// (x,x) with row stride FIN+2 ulls -> LDS.128 of (k,k+1) dup pairs is
// bank-conflict-free and the mainloop has zero pack MOVs.
template <int FIN, int FOUT, bool RELU, bool BIASH>
__global__ void __launch_bounds__(256)
k_gemm(const float* __restrict__ in, const float* __restrict__ W,
       const float* __restrict__ bh, float* __restrict__ out, int n) {
    constexpr int XR = FIN + 2;          // X row stride in ulls (conflict-free)
    extern __shared__ float sm[];
    float* Ws = sm;                      // [FIN][FOUT] floats
    ull*   Xs = reinterpret_cast<ull*>(sm + FIN * FOUT);   // [64][XR] dup pairs
    const int tid = threadIdx.x;
    const int base = blockIdx.x * 64;

    for (int i = tid; i < FIN * FOUT; i += 256) Ws[i] = W[i];

    const int rows = (n - base < 64) ? (n - base) : 64;
    constexpr int KQ = FIN / 4;
    for (int i = tid; i < 64 * KQ; i += 256) {
        int nl = i / KQ;
        int kq = i - nl * KQ;
        float4 v = {0.f, 0.f, 0.f, 0.f};
        if (nl < rows) {
            v = *reinterpret_cast<const float4*>(in + (size_t)(base + nl) * FIN + 4 * kq);
            if (RELU) {
                v.x = fmaxf(v.x, 0.f); v.y = fmaxf(v.y, 0.f);
                v.z = fmaxf(v.z, 0.f); v.w = fmaxf(v.w, 0.f);
            }
        }
        ull* xr = Xs + nl * XR + 4 * kq;
        ulonglong2 p0 = {dup2(v.x), dup2(v.y)};
        ulonglong2 p1 = {dup2(v.z), dup2(v.w)};
        *reinterpret_cast<ulonglong2*>(xr + 0) = p0;   // 16B aligned (4kq even)
        *reinterpret_cast<ulonglong2*>(xr + 2) = p1;
    }
    __syncthreads();

    const int lane = tid & 31;
    const int cg = tid >> 5;             // warp == col-group -> W reads broadcast
    constexpr int CH = FOUT / 8;         // 12 / 8 / 4 / 2 cols per thread
    constexpr int NP = CH / 2;           // packed accumulators per node (6/4/2/1)
    const int c0 = cg * CH;

    ull acc0[NP], acc1[NP];
#pragma unroll
    for (int j = 0; j < NP; j++) {
        ull b = BIASH ? *reinterpret_cast<const ull*>(bh + c0 + 2 * j) : 0ull;
        acc0[j] = b; acc1[j] = b;
    }

    const ull* x0 = Xs + (lane +  0) * XR;
    const ull* x1 = Xs + (lane + 32) * XR;

#pragma unroll 2
    for (int k = 0; k < FIN; k += 2) {
        ulonglong2 xa = *reinterpret_cast<const ulonglong2*>(x0 + k);
        ulonglong2 xb = *reinterpret_cast<const ulonglong2*>(x1 + k);
        const ull* w0 = reinterpret_cast<const ull*>(Ws + k * FOUT + c0);
        const ull* w1 = reinterpret_cast<const ull*>(Ws + (k + 1) * FOUT + c0);
#pragma unroll
        for (int j = 0; j < NP; j++) {
            ull wj0 = w0[j];
            acc0[j] = fma2(xa.x, wj0, acc0[j]);
            acc1[j] = fma2(xb.x, wj0, acc1[j]);
        }
#pragma unroll
        for (int j = 0; j < NP; j++) {
            ull wj1 = w1[j];
            acc0[j] = fma2(xa.y, wj1, acc0[j]);
            acc1[j] = fma2(xb.y, wj1, acc1[j]);
        }
    }

    {
        int node0 = base + lane;
        int node1 = base + lane + 32;
        if (node0 < n) {
            ull* op = reinterpret_cast<ull*>(out + (size_t)node0 * FOUT + c0);
#pragma unroll
            for (int j = 0; j < NP; j++) op[j] = acc0[j];
        }
        if (node1 < n) {
            ull* op = reinterpret_cast<ull*>(out + (size_t)node1 * FOUT + c0);
#pragma unroll
            for (int j = 0; j < NP; j++) op[j] = acc1[j];
        }
    }
}

// ---------------- launch -------------------------------------------------------
extern "C" void kernel_launch(void* const* d_in, const int* in_sizes, int n_in,
                              void* d_out, int out_size) {
    const float* x  = (const float*)d_in[0];
    const int*   ei = (const int*)d_in[1];   // int32
    const float* W1 = (const float*)d_in[2]; const float* b1 = (const float*)d_in[3];
    const float* W2 = (const float*)d_in[4]; const float* b2 = (const float*)d_in[5];
    const float* W3 = (const float*)d_in[6]; const float* b3 = (const float*)d_in[7];
    const float* W4 = (const float*)d_in[8]; const float* b4 = (const float*)d_in[9];
    float* out = (float*)d_out;

    const int n = in_sizes[0] / 64;
    const int e = in_sizes[1] / 2;

    float *bufA, *bufB, *bufH;
    cudaGetSymbolAddress((void**)&bufA, g_bufA);
    cudaGetSymbolAddress((void**)&bufB, g_bufB);
    cudaGetSymbolAddress((void**)&bufH, g_bufH);

    // smem: W floats + X dup pairs (64 x (FIN+2) ulls)
    const int s1 = 64 * 96 * 4 + 64 * 66 * 8;   // 24576 + 33792 = 58368
    const int s2 = 96 * 64 * 4 + 64 * 98 * 8;   // 24576 + 50176 = 74752
    const int s3 = 64 * 32 * 4 + 64 * 66 * 8;   //  8192 + 33792 = 41984
    const int s4 = 32 * 16 * 4 + 64 * 34 * 8;   //  2048 + 17408 = 19456
    cudaFuncSetAttribute(k_gemm<64, 96, false, true>, cudaFuncAttributeMaxDynamicSharedMemorySize, s1);
    cudaFuncSetAttribute(k_gemm<96, 64, true, false>, cudaFuncAttributeMaxDynamicSharedMemorySize, s2);
    cudaFuncSetAttribute(k_gemm<64, 32, true, false>, cudaFuncAttributeMaxDynamicSharedMemorySize, s3);
    cudaFuncSetAttribute(k_gemm<32, 16, true, false>, cudaFuncAttributeMaxDynamicSharedMemorySize, s4);

    const int TB = 256;
    const int nb_n = (n + TB - 1) / TB;
    const int nb_e = (e + TB - 1) / TB;
    const int gblk = (n + 63) / 64;

    // ---- CSR build: single edge pass (g_cur is zero on entry) ----
    k_bucketcount<<<nb_e, TB>>>(ei, e, n);
    k_dis<<<nb_n, TB>>>(n);

    // ---- layer 1: agg1 = Ax (width 64), then GEMM 64->96 (+b1) ----
    k_agg<64, false><<<(n * 16 + TB - 1) / TB, TB>>>(x, nullptr, bufA, n);
    k_gemm<64, 96, false, true><<<gblk, 256, s1>>>(bufA, W1, b1, bufB, n);

    // ---- layer 2: t = relu(h1)@W2 ; agg2 = A t + b2 ----
    k_gemm<96, 64, true, false><<<gblk, 256, s2>>>(bufB, W2, nullptr, bufH, n);
    k_agg<64, true><<<(n * 16 + TB - 1) / TB, TB>>>(bufH, b2, bufA, n);

    // ---- layer 3: t = relu(agg2)@W3 ; agg3 = A t + b3 ----
    k_gemm<64, 32, true, false><<<gblk, 256, s3>>>(bufA, W3, nullptr, bufH, n);
    k_agg<32, true><<<(n * 8 + TB - 1) / TB, TB>>>(bufH, b3, bufB, n);

    // ---- layer 4: t = relu(agg3)@W4 ; out = A t + b4 ----
    k_gemm<32, 16, true, false><<<gblk, 256, s4>>>(bufB, W4, nullptr, bufH, n);
    k_agg<16, true><<<(n * 4 + TB - 1) / TB, TB>>>(bufH, b4, out, n);

    // ---- reset cursor for the next (deterministic) replay ----
    k_zero_tail<<<nb_n, TB>>>(n);
}

// round 15
// speedup vs baseline: 1.1702x; 1.1702x over previous
#include <cuda_runtime.h>
#include <cuda_bf16.h>
#include <mma.h>
#include <cstdint>

using namespace nvcuda;
typedef unsigned long long ull;

// ---------------- problem constants ------------------------------------------
#define MAX_N 100000
#define MAX_E 1600000
#define MAXDEG 128
#define LOG2_MAXDEG 7
#define NPAD 100096            // 782 * 128  (MMA tiles write full rows)

// ---------------- device scratch (allocation-free; static zero-init) ----------
__device__ int   g_cur[MAX_N];                 // bucket cursor == degree after pass
__device__ float g_dis[MAX_N];                 // (deg+1)^{-1/2}
__device__ int   g_eslot[MAX_N * MAXDEG];      // fixed-stride CSR: src ids
__device__ __align__(16) float g_bufA[NPAD * 96];
__device__ __align__(16) float g_bufB[NPAD * 96];
__device__ __align__(16) float g_bufH[NPAD * 96];
// W images [KS rows][FOUT] row-major, split hi/lo bf16. Row FIN = bias (layer 1).
// Pad rows (> written range) are never written -> stay zero from static init.
__device__ __align__(16) __nv_bfloat16 g_whi[4][8192];
__device__ __align__(16) __nv_bfloat16 g_wlo[4][8192];

__device__ __forceinline__ ull pk4(__nv_bfloat16 a, __nv_bfloat16 b,
                                   __nv_bfloat16 c, __nv_bfloat16 d) {
    return (ull)__bfloat16_as_ushort(a)
         | ((ull)__bfloat16_as_ushort(b) << 16)
         | ((ull)__bfloat16_as_ushort(c) << 32)
         | ((ull)__bfloat16_as_ushort(d) << 48);
}

// ---------------- CSR build (unchanged from best) -------------------------------
__global__ void k_bucketcount(const int* __restrict__ ei, int e, int n) {
    int i = blockIdx.x * blockDim.x + threadIdx.x;
    if (i >= e) return;
    int s = ei[i];
    int d = ei[e + i];
    if ((unsigned)s >= (unsigned)n) s = 0;
    if ((unsigned)d >= (unsigned)n) d = 0;
    int pos = atomicAdd(&g_cur[d], 1);
    if (pos < MAXDEG) g_eslot[(d << LOG2_MAXDEG) + pos] = s;
}
__global__ void k_dis(int n) {
    int i = blockIdx.x * blockDim.x + threadIdx.x;
    if (i < n) g_dis[i] = rsqrtf((float)g_cur[i] + 1.0f);
}
__global__ void k_zero_tail(int n) {
    int i = blockIdx.x * blockDim.x + threadIdx.x;
    if (i < n) g_cur[i] = 0;
}

// ---------------- W split into hi/lo images (row-major, + bias row L1) ---------
__global__ void k_splitW(const float* __restrict__ W1, const float* __restrict__ b1,
                         const float* __restrict__ W2, const float* __restrict__ W3,
                         const float* __restrict__ W4) {
    int idx = blockIdx.x * 256 + threadIdx.x;
    const float* W; const float* bv; int layer, FIN, FOUT, local;
    if (idx < 6240)       { layer = 0; W = W1; bv = b1;      FIN = 64; FOUT = 96; local = idx; }          // 65 rows
    else if (idx < 12384) { layer = 1; W = W2; bv = nullptr; FIN = 96; FOUT = 64; local = idx - 6240; }
    else if (idx < 14432) { layer = 2; W = W3; bv = nullptr; FIN = 64; FOUT = 32; local = idx - 12384; }
    else if (idx < 14944) { layer = 3; W = W4; bv = nullptr; FIN = 32; FOUT = 16; local = idx - 14432; }
    else return;
    int krow = local / FOUT;
    int col = local - krow * FOUT;
    float v = (krow < FIN) ? W[krow * FOUT + col] : bv[col];
    __nv_bfloat16 h = __float2bfloat16(v);
    __nv_bfloat16 l = __float2bfloat16(v - __bfloat162float(h));
    g_whi[layer][krow * FOUT + col] = h;
    g_wlo[layer][krow * FOUT + col] = l;
}

// ---------------- gather aggregation (unchanged from best) ---------------------
template <int F, bool BIAS>
__global__ void __launch_bounds__(256)
k_agg(const float* __restrict__ h, const float* __restrict__ bias,
      float* __restrict__ out, int n) {
    constexpr int G = F / 4;
    int tid = blockIdx.x * blockDim.x + threadIdx.x;
    int node = tid / G;
    int v = tid - node * G;
    if (node >= n) return;

    float dn = g_dis[node];
    float d2 = dn * dn;
    float4 acc = *reinterpret_cast<const float4*>(h + (size_t)node * F + (v << 2));
    acc.x *= d2; acc.y *= d2; acc.z *= d2; acc.w *= d2;
    if (BIAS) {
        float4 bv = *reinterpret_cast<const float4*>(bias + (v << 2));
        acc.x += bv.x; acc.y += bv.y; acc.z += bv.z; acc.w += bv.w;
    }
    int deg = g_cur[node];
    if (deg > MAXDEG) deg = MAXDEG;
    const int* slots = g_eslot + ((size_t)node << LOG2_MAXDEG);
    int j = 0;
    for (; j + 4 <= deg; j += 4) {
        int4 s4 = *reinterpret_cast<const int4*>(slots + j);
        float w0 = g_dis[s4.x] * dn;
        float w1 = g_dis[s4.y] * dn;
        float w2 = g_dis[s4.z] * dn;
        float w3 = g_dis[s4.w] * dn;
        float4 a0 = *reinterpret_cast<const float4*>(h + (size_t)s4.x * F + (v << 2));
        float4 a1 = *reinterpret_cast<const float4*>(h + (size_t)s4.y * F + (v << 2));
        float4 a2 = *reinterpret_cast<const float4*>(h + (size_t)s4.z * F + (v << 2));
        float4 a3 = *reinterpret_cast<const float4*>(h + (size_t)s4.w * F + (v << 2));
        acc.x += a0.x * w0; acc.y += a0.y * w0; acc.z += a0.z * w0; acc.w += a0.w * w0;
        acc.x += a1.x * w1; acc.y += a1.y * w1; acc.z += a1.z * w1; acc.w += a1.w * w1;
        acc.x += a2.x * w2; acc.y += a2.y * w2; acc.z += a2.z * w2; acc.w += a2.w * w2;
        acc.x += a3.x * w3; acc.y += a3.y * w3; acc.z += a3.z * w3; acc.w += a3.w * w3;
    }
    for (; j < deg; j++) {
        int s = slots[j];
        float w = g_dis[s] * dn;
        float4 a = *reinterpret_cast<const float4*>(h + (size_t)s * F + (v << 2));
        acc.x += a.x * w; acc.y += a.y * w; acc.z += a.z * w; acc.w += a.w * w;
    }
    *reinterpret_cast<float4*>(out + (size_t)node * F + (v << 2)) = acc;
}

// ---------------- WMMA GEMM: out[128-tile] = act(in) @ W (+bias-K-row) ---------
// Split-bf16 x3: D = Ahi*Whi + Ahi*Wlo + Alo*Whi (fp32 acc). 8 warps x 16 rows.
// Bias (layer 1) folded as K-row FIN with A ones-column. Output buffer is padded
// to NPAD rows so full-tile stores are always in-bounds.
template <int FIN, int FOUT, int KS, bool RELU, bool BIASH>
__global__ void __launch_bounds__(256)
k_wmma(const float* __restrict__ in, const __nv_bfloat16* __restrict__ wh,
       const __nv_bfloat16* __restrict__ wl, float* __restrict__ out, int n) {
    constexpr int XLD = KS + 8;          // A smem leading dim (mult of 8)
    constexpr int KQ = KS / 4;
    constexpr int KSTEPS = KS / 16;
    constexpr int NT = FOUT / 16;
    extern __shared__ __nv_bfloat16 sm[];
    __nv_bfloat16* Ahi = sm;                          // [128][XLD]
    __nv_bfloat16* Alo = Ahi + 128 * XLD;
    __nv_bfloat16* Whi = Alo + 128 * XLD;             // [KS][FOUT]
    __nv_bfloat16* Wlo = Whi + KS * FOUT;
    const int tid = threadIdx.x;
    const int wid = tid >> 5;
    const int base = blockIdx.x * 128;
    const int rows = (n - base < 128) ? (n - base) : 128;

    // copy W images
    {
        const ulonglong2* sh = reinterpret_cast<const ulonglong2*>(wh);
        const ulonglong2* sl = reinterpret_cast<const ulonglong2*>(wl);
        ulonglong2* dh = reinterpret_cast<ulonglong2*>(Whi);
        ulonglong2* dl = reinterpret_cast<ulonglong2*>(Wlo);
        for (int i = tid; i < KS * FOUT / 8; i += 256) { dh[i] = sh[i]; dl[i] = sl[i]; }
    }
    // stage A: relu -> split hi/lo; ones column at k==FIN when BIASH; zero pad
    for (int i = tid; i < 128 * KQ; i += 256) {
        int nl = i / KQ;
        int k4 = (i - nl * KQ) << 2;
        ull phi = 0, plo = 0;
        if (k4 < FIN) {
            if (nl < rows) {
                float4 v = *reinterpret_cast<const float4*>(in + (size_t)(base + nl) * FIN + k4);
                if (RELU) {
                    v.x = fmaxf(v.x, 0.f); v.y = fmaxf(v.y, 0.f);
                    v.z = fmaxf(v.z, 0.f); v.w = fmaxf(v.w, 0.f);
                }
                __nv_bfloat16 h0 = __float2bfloat16(v.x), h1 = __float2bfloat16(v.y);
                __nv_bfloat16 h2 = __float2bfloat16(v.z), h3 = __float2bfloat16(v.w);
                __nv_bfloat16 l0 = __float2bfloat16(v.x - __bfloat162float(h0));
                __nv_bfloat16 l1 = __float2bfloat16(v.y - __bfloat162float(h1));
                __nv_bfloat16 l2 = __float2bfloat16(v.z - __bfloat162float(h2));
                __nv_bfloat16 l3 = __float2bfloat16(v.w - __bfloat162float(h3));
                phi = pk4(h0, h1, h2, h3);
                plo = pk4(l0, l1, l2, l3);
            }
        } else if (BIASH && k4 == FIN) {
            phi = 0x3F80ull;                      // bf16 1.0 in element 0
        }
        *reinterpret_cast<ull*>(Ahi + nl * XLD + k4) = phi;
        *reinterpret_cast<ull*>(Alo + nl * XLD + k4) = plo;
    }
    __syncthreads();

    wmma::fragment<wmma::accumulator, 16, 16, 16, float> acc[NT];
#pragma unroll
    for (int t = 0; t < NT; t++) wmma::fill_fragment(acc[t], 0.0f);

    const __nv_bfloat16* arow = Ahi + (wid * 16) * XLD;
    const __nv_bfloat16* arol = Alo + (wid * 16) * XLD;
#pragma unroll
    for (int ks = 0; ks < KSTEPS; ks++) {
        wmma::fragment<wmma::matrix_a, 16, 16, 16, __nv_bfloat16, wmma::row_major> ah, al;
        wmma::load_matrix_sync(ah, arow + ks * 16, XLD);
        wmma::load_matrix_sync(al, arol + ks * 16, XLD);
#pragma unroll
        for (int t = 0; t < NT; t++) {
            wmma::fragment<wmma::matrix_b, 16, 16, 16, __nv_bfloat16, wmma::row_major> bhf, blf;
            wmma::load_matrix_sync(bhf, Whi + ks * 16 * FOUT + t * 16, FOUT);
            wmma::load_matrix_sync(blf, Wlo + ks * 16 * FOUT + t * 16, FOUT);
            wmma::mma_sync(acc[t], ah, bhf, acc[t]);
            wmma::mma_sync(acc[t], ah, blf, acc[t]);
            wmma::mma_sync(acc[t], al, bhf, acc[t]);
        }
    }

    float* orow = out + (size_t)(base + wid * 16) * FOUT;
#pragma unroll
    for (int t = 0; t < NT; t++)
        wmma::store_matrix_sync(orow + t * 16, acc[t], FOUT, wmma::mem_row_major);
}

// ---------------- launch -------------------------------------------------------
extern "C" void kernel_launch(void* const* d_in, const int* in_sizes, int n_in,
                              void* d_out, int out_size) {
    const float* x  = (const float*)d_in[0];
    const int*   ei = (const int*)d_in[1];   // int32
    const float* W1 = (const float*)d_in[2]; const float* b1 = (const float*)d_in[3];
    const float* W2 = (const float*)d_in[4]; const float* b2 = (const float*)d_in[5];
    const float* W3 = (const float*)d_in[6]; const float* b3 = (const float*)d_in[7];
    const float* W4 = (const float*)d_in[8]; const float* b4 = (const float*)d_in[9];
    float* out = (float*)d_out;

    const int n = in_sizes[0] / 64;
    const int e = in_sizes[1] / 2;

    float *bufA, *bufB, *bufH;
    cudaGetSymbolAddress((void**)&bufA, g_bufA);
    cudaGetSymbolAddress((void**)&bufB, g_bufB);
    cudaGetSymbolAddress((void**)&bufH, g_bufH);
    __nv_bfloat16 *whi, *wlo;
    cudaGetSymbolAddress((void**)&whi, g_whi);
    cudaGetSymbolAddress((void**)&wlo, g_wlo);

    // smem bytes: 2*128*XLD*2 + 2*KS*FOUT*2
    const int s1 = (2 * 128 * 88  + 2 * 80 * 96) * 2;   // 75776  (KS=80)
    const int s2 = (2 * 128 * 104 + 2 * 96 * 64) * 2;   // 77824  (KS=96)
    const int s3 = (2 * 128 * 72  + 2 * 64 * 32) * 2;   // 45056  (KS=64)
    const int s4 = (2 * 128 * 40  + 2 * 32 * 16) * 2;   // 22528  (KS=32)
    cudaFuncSetAttribute(k_wmma<64, 96, 80, false, true>, cudaFuncAttributeMaxDynamicSharedMemorySize, s1);
    cudaFuncSetAttribute(k_wmma<96, 64, 96, true, false>, cudaFuncAttributeMaxDynamicSharedMemorySize, s2);
    cudaFuncSetAttribute(k_wmma<64, 32, 64, true, false>, cudaFuncAttributeMaxDynamicSharedMemorySize, s3);
    cudaFuncSetAttribute(k_wmma<32, 16, 32, true, false>, cudaFuncAttributeMaxDynamicSharedMemorySize, s4);

    const int TB = 256;
    const int nb_n = (n + TB - 1) / TB;
    const int nb_e = (e + TB - 1) / TB;
    const int gblk = (n + 127) / 128;

    // ---- CSR build + W split images ----
    k_bucketcount<<<nb_e, TB>>>(ei, e, n);
    k_dis<<<nb_n, TB>>>(n);
    k_splitW<<<59, 256>>>(W1, b1, W2, W3, W4);

    // ---- layer 1: agg1 = Ax (width 64), then WMMA 64->96 (+b1 via K-row) ----
    k_agg<64, false><<<(n * 16 + TB - 1) / TB, TB>>>(x, nullptr, bufA, n);
    k_wmma<64, 96, 80, false, true><<<gblk, 256, s1>>>(bufA, whi + 0 * 8192, wlo + 0 * 8192, bufB, n);

    // ---- layer 2: t = relu(h1)@W2 ; agg2 = A t + b2 ----
    k_wmma<96, 64, 96, true, false><<<gblk, 256, s2>>>(bufB, whi + 1 * 8192, wlo + 1 * 8192, bufH, n);
    k_agg<64, true><<<(n * 16 + TB - 1) / TB, TB>>>(bufH, b2, bufA, n);

    // ---- layer 3: t = relu(agg2)@W3 ; agg3 = A t + b3 ----
    k_wmma<64, 32, 64, true, false><<<gblk, 256, s3>>>(bufA, whi + 2 * 8192, wlo + 2 * 8192, bufH, n);
    k_agg<32, true><<<(n * 8 + TB - 1) / TB, TB>>>(bufH, b3, bufB, n);

    // ---- layer 4: t = relu(agg3)@W4 ; out = A t + b4 ----
    k_wmma<32, 16, 32, true, false><<<gblk, 256, s4>>>(bufB, whi + 3 * 8192, wlo + 3 * 8192, bufH, n);
    k_agg<16, true><<<(n * 4 + TB - 1) / TB, TB>>>(bufH, b4, out, n);

    // ---- reset cursor for the next (deterministic) replay ----
    k_zero_tail<<<nb_n, TB>>>(n);
}

// round 16
// speedup vs baseline: 1.1930x; 1.0195x over previous
#include <cuda_runtime.h>
#include <cuda_bf16.h>
#include <cuda_fp16.h>
#include <mma.h>
#include <cstdint>

using namespace nvcuda;
typedef unsigned long long ull;

// ---------------- problem constants ------------------------------------------
#define MAX_N 100000
#define MAX_E 1600000
#define MAXDEG 128
#define LOG2_MAXDEG 7
#define NPAD 100096            // 782 * 128  (MMA tiles write full rows)

// ---------------- device scratch (allocation-free; static zero-init) ----------
__device__ int   g_cur[MAX_N];                 // bucket cursor (zeroed in k_dis)
__device__ int   g_deg[MAX_N];                 // saved degree
__device__ float g_dis[MAX_N];                 // (deg+1)^{-1/2}
__device__ int   g_eslot[MAX_N * MAXDEG];      // fixed-stride CSR: src ids
__device__ __align__(16) float g_bufA[NPAD * 96];   // fp32 g-values
__device__ __align__(16) float g_bufB[NPAD * 96];   // fp32 g1 / half t3
__device__ __align__(16) float g_bufH[NPAD * 96];   // half xh / t2 / t4
__device__ __align__(16) __nv_bfloat16 g_whi[4][8192];
__device__ __align__(16) __nv_bfloat16 g_wlo[4][8192];

__device__ __forceinline__ ull pk4(__nv_bfloat16 a, __nv_bfloat16 b,
                                   __nv_bfloat16 c, __nv_bfloat16 d) {
    return (ull)__bfloat16_as_ushort(a)
         | ((ull)__bfloat16_as_ushort(b) << 16)
         | ((ull)__bfloat16_as_ushort(c) << 32)
         | ((ull)__bfloat16_as_ushort(d) << 48);
}
__device__ __forceinline__ float4 ldh4(const __half* p) {
    uint2 r = *reinterpret_cast<const uint2*>(p);
    __half2 a = *reinterpret_cast<__half2*>(&r.x);
    __half2 b = *reinterpret_cast<__half2*>(&r.y);
    float2 fa = __half22float2(a), fb = __half22float2(b);
    return make_float4(fa.x, fa.y, fb.x, fb.y);
}

// ---------------- CSR build -----------------------------------------------------
__global__ void k_bucketcount(const int* __restrict__ ei, int e, int n) {
    int i = blockIdx.x * blockDim.x + threadIdx.x;
    if (i >= e) return;
    int s = ei[i];
    int d = ei[e + i];
    if ((unsigned)s >= (unsigned)n) s = 0;
    if ((unsigned)d >= (unsigned)n) d = 0;
    int pos = atomicAdd(&g_cur[d], 1);
    if (pos < MAXDEG) g_eslot[(d << LOG2_MAXDEG) + pos] = s;
}
// saves degree, computes dis, resets cursor for next replay (fuses zero_tail)
__global__ void k_dis(int n) {
    int i = blockIdx.x * blockDim.x + threadIdx.x;
    if (i >= n) return;
    int d = g_cur[i];
    g_deg[i] = d;
    g_cur[i] = 0;
    g_dis[i] = rsqrtf((float)d + 1.0f);
}

// ---------------- x -> fp16 image ----------------------------------------------
__global__ void k_tohalf(const float* __restrict__ x, __half* __restrict__ xh, int n4) {
    int i = blockIdx.x * blockDim.x + threadIdx.x;
    if (i >= n4) return;
    float4 v = reinterpret_cast<const float4*>(x)[i];
    __half2* o = reinterpret_cast<__half2*>(xh) + 2 * i;
    o[0] = __floats2half2_rn(v.x, v.y);
    o[1] = __floats2half2_rn(v.z, v.w);
}

// ---------------- W split into hi/lo images (row-major, + bias row L1) ---------
__global__ void k_splitW(const float* __restrict__ W1, const float* __restrict__ b1,
                         const float* __restrict__ W2, const float* __restrict__ W3,
                         const float* __restrict__ W4) {
    int idx = blockIdx.x * 256 + threadIdx.x;
    const float* W; const float* bv; int layer, FIN, FOUT, local;
    if (idx < 6240)       { layer = 0; W = W1; bv = b1;      FIN = 64; FOUT = 96; local = idx; }
    else if (idx < 12384) { layer = 1; W = W2; bv = nullptr; FIN = 96; FOUT = 64; local = idx - 6240; }
    else if (idx < 14432) { layer = 2; W = W3; bv = nullptr; FIN = 64; FOUT = 32; local = idx - 12384; }
    else if (idx < 14944) { layer = 3; W = W4; bv = nullptr; FIN = 32; FOUT = 16; local = idx - 14432; }
    else return;
    int krow = local / FOUT;
    int col = local - krow * FOUT;
    float v = (krow < FIN) ? W[krow * FOUT + col] : bv[col];
    __nv_bfloat16 h = __float2bfloat16(v);
    __nv_bfloat16 l = __float2bfloat16(v - __bfloat162float(h));
    g_whi[layer][krow * FOUT + col] = h;
    g_wlo[layer][krow * FOUT + col] = l;
}

// ---------------- gather aggregation (fp16 features in, fp32 out) --------------
template <int F, bool BIAS>
__global__ void __launch_bounds__(256)
k_agg(const __half* __restrict__ h, const float* __restrict__ bias,
      float* __restrict__ out, int n) {
    constexpr int G = F / 4;
    int tid = blockIdx.x * blockDim.x + threadIdx.x;
    int node = tid / G;
    int v = tid - node * G;
    if (node >= n) return;

    float dn = g_dis[node];
    float d2 = dn * dn;
    float4 acc = ldh4(h + (size_t)node * F + (v << 2));
    acc.x *= d2; acc.y *= d2; acc.z *= d2; acc.w *= d2;
    if (BIAS) {
        float4 bv = *reinterpret_cast<const float4*>(bias + (v << 2));
        acc.x += bv.x; acc.y += bv.y; acc.z += bv.z; acc.w += bv.w;
    }
    int deg = g_deg[node];
    if (deg > MAXDEG) deg = MAXDEG;
    const int* slots = g_eslot + ((size_t)node << LOG2_MAXDEG);
    int j = 0;
    for (; j + 4 <= deg; j += 4) {
        int4 s4 = *reinterpret_cast<const int4*>(slots + j);
        float w0 = g_dis[s4.x] * dn;
        float w1 = g_dis[s4.y] * dn;
        float w2 = g_dis[s4.z] * dn;
        float w3 = g_dis[s4.w] * dn;
        float4 a0 = ldh4(h + (size_t)s4.x * F + (v << 2));
        float4 a1 = ldh4(h + (size_t)s4.y * F + (v << 2));
        float4 a2 = ldh4(h + (size_t)s4.z * F + (v << 2));
        float4 a3 = ldh4(h + (size_t)s4.w * F + (v << 2));
        acc.x += a0.x * w0; acc.y += a0.y * w0; acc.z += a0.z * w0; acc.w += a0.w * w0;
        acc.x += a1.x * w1; acc.y += a1.y * w1; acc.z += a1.z * w1; acc.w += a1.w * w1;
        acc.x += a2.x * w2; acc.y += a2.y * w2; acc.z += a2.z * w2; acc.w += a2.w * w2;
        acc.x += a3.x * w3; acc.y += a3.y * w3; acc.z += a3.z * w3; acc.w += a3.w * w3;
    }
    for (; j < deg; j++) {
        int s = slots[j];
        float w = g_dis[s] * dn;
        float4 a = ldh4(h + (size_t)s * F + (v << 2));
        acc.x += a.x * w; acc.y += a.y * w; acc.z += a.z * w; acc.w += a.w * w;
    }
    *reinterpret_cast<float4*>(out + (size_t)node * F + (v << 2)) = acc;
}

// ---------------- WMMA GEMM: split-bf16 x3, fp32 acc ---------------------------
// OUTH=false: store fp32 direct. OUTH=true: frags -> smem fp32 tile -> half2 gmem.
template <int FIN, int FOUT, int KS, bool RELU, bool BIASH, bool OUTH>
__global__ void __launch_bounds__(256)
k_wmma(const float* __restrict__ in, const __nv_bfloat16* __restrict__ wh,
       const __nv_bfloat16* __restrict__ wl, void* __restrict__ outp, int n) {
    constexpr int XLD = KS + 8;
    constexpr int KQ = KS / 4;
    constexpr int KSTEPS = KS / 16;
    constexpr int NT = FOUT / 16;
    extern __shared__ __nv_bfloat16 sm[];
    __nv_bfloat16* Ahi = sm;                          // [128][XLD]
    __nv_bfloat16* Alo = Ahi + 128 * XLD;
    __nv_bfloat16* Whi = Alo + 128 * XLD;             // [KS][FOUT]
    __nv_bfloat16* Wlo = Whi + KS * FOUT;
    const int tid = threadIdx.x;
    const int wid = tid >> 5;
    const int base = blockIdx.x * 128;
    const int rows = (n - base < 128) ? (n - base) : 128;

    {
        const ulonglong2* sh = reinterpret_cast<const ulonglong2*>(wh);
        const ulonglong2* sl = reinterpret_cast<const ulonglong2*>(wl);
        ulonglong2* dh = reinterpret_cast<ulonglong2*>(Whi);
        ulonglong2* dl = reinterpret_cast<ulonglong2*>(Wlo);
        for (int i = tid; i < KS * FOUT / 8; i += 256) { dh[i] = sh[i]; dl[i] = sl[i]; }
    }
    for (int i = tid; i < 128 * KQ; i += 256) {
        int nl = i / KQ;
        int k4 = (i - nl * KQ) << 2;
        ull phi = 0, plo = 0;
        if (k4 < FIN) {
            if (nl < rows) {
                float4 v = *reinterpret_cast<const float4*>(in + (size_t)(base + nl) * FIN + k4);
                if (RELU) {
                    v.x = fmaxf(v.x, 0.f); v.y = fmaxf(v.y, 0.f);
                    v.z = fmaxf(v.z, 0.f); v.w = fmaxf(v.w, 0.f);
                }
                __nv_bfloat16 h0 = __float2bfloat16(v.x), h1 = __float2bfloat16(v.y);
                __nv_bfloat16 h2 = __float2bfloat16(v.z), h3 = __float2bfloat16(v.w);
                __nv_bfloat16 l0 = __float2bfloat16(v.x - __bfloat162float(h0));
                __nv_bfloat16 l1 = __float2bfloat16(v.y - __bfloat162float(h1));
                __nv_bfloat16 l2 = __float2bfloat16(v.z - __bfloat162float(h2));
                __nv_bfloat16 l3 = __float2bfloat16(v.w - __bfloat162float(h3));
                phi = pk4(h0, h1, h2, h3);
                plo = pk4(l0, l1, l2, l3);
            }
        } else if (BIASH && k4 == FIN) {
            phi = 0x3F80ull;                      // bf16 1.0 (ones column)
        }
        *reinterpret_cast<ull*>(Ahi + nl * XLD + k4) = phi;
        *reinterpret_cast<ull*>(Alo + nl * XLD + k4) = plo;
    }
    __syncthreads();

    wmma::fragment<wmma::accumulator, 16, 16, 16, float> acc[NT];
#pragma unroll
    for (int t = 0; t < NT; t++) wmma::fill_fragment(acc[t], 0.0f);

    const __nv_bfloat16* arow = Ahi + (wid * 16) * XLD;
    const __nv_bfloat16* arol = Alo + (wid * 16) * XLD;
#pragma unroll
    for (int ks = 0; ks < KSTEPS; ks++) {
        wmma::fragment<wmma::matrix_a, 16, 16, 16, __nv_bfloat16, wmma::row_major> ah, al;
        wmma::load_matrix_sync(ah, arow + ks * 16, XLD);
        wmma::load_matrix_sync(al, arol + ks * 16, XLD);
#pragma unroll
        for (int t = 0; t < NT; t++) {
            wmma::fragment<wmma::matrix_b, 16, 16, 16, __nv_bfloat16, wmma::row_major> bhf, blf;
            wmma::load_matrix_sync(bhf, Whi + ks * 16 * FOUT + t * 16, FOUT);
            wmma::load_matrix_sync(blf, Wlo + ks * 16 * FOUT + t * 16, FOUT);
            wmma::mma_sync(acc[t], ah, bhf, acc[t]);
            wmma::mma_sync(acc[t], ah, blf, acc[t]);
            wmma::mma_sync(acc[t], al, bhf, acc[t]);
        }
    }

    if (!OUTH) {
        float* orow = reinterpret_cast<float*>(outp) + (size_t)(base + wid * 16) * FOUT;
#pragma unroll
        for (int t = 0; t < NT; t++)
            wmma::store_matrix_sync(orow + t * 16, acc[t], FOUT, wmma::mem_row_major);
    } else {
        __syncthreads();                           // staging reads done; reuse smem
        float* Ot = reinterpret_cast<float*>(sm);  // [128][FOUT] fp32 tile
        float* orow = Ot + (wid * 16) * FOUT;
#pragma unroll
        for (int t = 0; t < NT; t++)
            wmma::store_matrix_sync(orow + t * 16, acc[t], FOUT, wmma::mem_row_major);
        __syncthreads();
        __half2* og = reinterpret_cast<__half2*>(
            reinterpret_cast<__half*>(outp) + (size_t)base * FOUT);
        for (int i = tid; i < 128 * FOUT / 2; i += 256)
            og[i] = __floats2half2_rn(Ot[2 * i], Ot[2 * i + 1]);
    }
}

// ---------------- launch -------------------------------------------------------
extern "C" void kernel_launch(void* const* d_in, const int* in_sizes, int n_in,
                              void* d_out, int out_size) {
    const float* x  = (const float*)d_in[0];
    const int*   ei = (const int*)d_in[1];   // int32
    const float* W1 = (const float*)d_in[2]; const float* b1 = (const float*)d_in[3];
    const float* W2 = (const float*)d_in[4]; const float* b2 = (const float*)d_in[5];
    const float* W3 = (const float*)d_in[6]; const float* b3 = (const float*)d_in[7];
    const float* W4 = (const float*)d_in[8]; const float* b4 = (const float*)d_in[9];
    float* out = (float*)d_out;

    const int n = in_sizes[0] / 64;
    const int e = in_sizes[1] / 2;

    float *bufA, *bufB, *bufH;
    cudaGetSymbolAddress((void**)&bufA, g_bufA);
    cudaGetSymbolAddress((void**)&bufB, g_bufB);
    cudaGetSymbolAddress((void**)&bufH, g_bufH);
    __nv_bfloat16 *whi, *wlo;
    cudaGetSymbolAddress((void**)&whi, g_whi);
    cudaGetSymbolAddress((void**)&wlo, g_wlo);
    __half* xh = (__half*)bufH;      // x fp16 image (dead after agg1)
    __half* t2 = (__half*)bufH;      // t2 overwrites xh (after wmma1 consumed A1)
    __half* t3 = (__half*)bufB;      // g1 dead after wmma2
    __half* t4 = (__half*)bufH;      // t2 dead after agg2... (after wmma3) reuse

    // smem: staging (2*128*XLD + 2*KS*FOUT) bf16; OUTH tile reuses staging region
    const int s1 = (2 * 128 * 88  + 2 * 80 * 96) * 2;   // 75776
    const int s2 = (2 * 128 * 104 + 2 * 96 * 64) * 2;   // 77824 (>= 128*64*4)
    const int s3 = (2 * 128 * 72  + 2 * 64 * 32) * 2;   // 45056 (>= 128*32*4)
    const int s4 = (2 * 128 * 40  + 2 * 32 * 16) * 2;   // 22528 (>= 128*16*4)
    cudaFuncSetAttribute(k_wmma<64, 96, 80, false, true,  false>, cudaFuncAttributeMaxDynamicSharedMemorySize, s1);
    cudaFuncSetAttribute(k_wmma<96, 64, 96, true,  false, true>,  cudaFuncAttributeMaxDynamicSharedMemorySize, s2);
    cudaFuncSetAttribute(k_wmma<64, 32, 64, true,  false, true>,  cudaFuncAttributeMaxDynamicSharedMemorySize, s3);
    cudaFuncSetAttribute(k_wmma<32, 16, 32, true,  false, true>,  cudaFuncAttributeMaxDynamicSharedMemorySize, s4);

    const int TB = 256;
    const int nb_n = (n + TB - 1) / TB;
    const int nb_e = (e + TB - 1) / TB;
    const int gblk = (n + 127) / 128;

    // ---- CSR build + W split images + x fp16 image ----
    k_bucketcount<<<nb_e, TB>>>(ei, e, n);
    k_dis<<<nb_n, TB>>>(n);                  // also resets cursor for next replay
    k_splitW<<<59, 256>>>(W1, b1, W2, W3, W4);
    k_tohalf<<<(n * 16 + TB - 1) / TB, TB>>>(x, xh, n * 16);

    // ---- layer 1: A1 = A_hat x (width 64, fp16 gather), g1 = A1@W1 + b1 ----
    k_agg<64, false><<<(n * 16 + TB - 1) / TB, TB>>>(xh, nullptr, bufA, n);
    k_wmma<64, 96, 80, false, true, false><<<gblk, 256, s1>>>(bufA, whi + 0 * 8192, wlo + 0 * 8192, bufB, n);

    // ---- layer 2: t2 = relu(g1)@W2 (half out); g2 = A_hat t2 + b2 ----
    k_wmma<96, 64, 96, true, false, true><<<gblk, 256, s2>>>(bufB, whi + 1 * 8192, wlo + 1 * 8192, t2, n);
    k_agg<64, true><<<(n * 16 + TB - 1) / TB, TB>>>(t2, b2, bufA, n);

    // ---- layer 3: t3 = relu(g2)@W3 (half out); g3 = A_hat t3 + b3 ----
    k_wmma<64, 32, 64, true, false, true><<<gblk, 256, s3>>>(bufA, whi + 2 * 8192, wlo + 2 * 8192, t3, n);
    k_agg<32, true><<<(n * 8 + TB - 1) / TB, TB>>>(t3, b3, bufA, n);

    // ---- layer 4: t4 = relu(g3)@W4 (half out); out = A_hat t4 + b4 ----
    k_wmma<32, 16, 32, true, false, true><<<gblk, 256, s4>>>(bufA, whi + 3 * 8192, wlo + 3 * 8192, t4, n);
    k_agg<16, true><<<(n * 4 + TB - 1) / TB, TB>>>(t4, b4, out, n);
}

// round 17
// speedup vs baseline: 1.2127x; 1.0164x over previous
#include <cuda_runtime.h>
#include <cuda_bf16.h>
#include <cuda_fp16.h>
#include <mma.h>
#include <cstdint>

using namespace nvcuda;
typedef unsigned long long ull;

// ---------------- problem constants ------------------------------------------
#define MAX_N 100000
#define MAX_E 1600000
#define MAXDEG 128
#define LOG2_MAXDEG 7
#define NPAD 100096            // 782 * 128  (MMA tiles write full rows)

// ---------------- device scratch (allocation-free; static zero-init) ----------
__device__ int   g_cur[MAX_N];                 // bucket cursor (zeroed in k_dis)
__device__ int   g_deg[MAX_N];                 // saved degree
__device__ float g_dis[MAX_N];                 // (deg+1)^{-1/2}
__device__ int   g_eslot[MAX_N * MAXDEG];      // fixed-stride CSR: src ids
__device__ __align__(16) float g_bufA[NPAD * 96];   // fp32 g-values
__device__ __align__(16) float g_bufB[NPAD * 96];   // fp32 g1 / half t3
__device__ __align__(16) float g_bufH[NPAD * 96];   // half xh / t2 / t4
__device__ __align__(16) __nv_bfloat16 g_whi[4][8192];
__device__ __align__(16) __nv_bfloat16 g_wlo[4][8192];

__device__ __forceinline__ ull pk4(__nv_bfloat16 a, __nv_bfloat16 b,
                                   __nv_bfloat16 c, __nv_bfloat16 d) {
    return (ull)__bfloat16_as_ushort(a)
         | ((ull)__bfloat16_as_ushort(b) << 16)
         | ((ull)__bfloat16_as_ushort(c) << 32)
         | ((ull)__bfloat16_as_ushort(d) << 48);
}
// 16B gather: 8 halves -> 8 floats
__device__ __forceinline__ void ldh8(const __half* p, float* f) {
    int4 r = *reinterpret_cast<const int4*>(p);
    __half2 h0 = *reinterpret_cast<__half2*>(&r.x);
    __half2 h1 = *reinterpret_cast<__half2*>(&r.y);
    __half2 h2 = *reinterpret_cast<__half2*>(&r.z);
    __half2 h3 = *reinterpret_cast<__half2*>(&r.w);
    float2 f0 = __half22float2(h0), f1 = __half22float2(h1);
    float2 f2 = __half22float2(h2), f3 = __half22float2(h3);
    f[0] = f0.x; f[1] = f0.y; f[2] = f1.x; f[3] = f1.y;
    f[4] = f2.x; f[5] = f2.y; f[6] = f3.x; f[7] = f3.y;
}

// ---------------- CSR build -----------------------------------------------------
__global__ void k_bucketcount(const int* __restrict__ ei, int e, int n) {
    int i = blockIdx.x * blockDim.x + threadIdx.x;
    if (i >= e) return;
    int s = ei[i];
    int d = ei[e + i];
    if ((unsigned)s >= (unsigned)n) s = 0;
    if ((unsigned)d >= (unsigned)n) d = 0;
    int pos = atomicAdd(&g_cur[d], 1);
    if (pos < MAXDEG) g_eslot[(d << LOG2_MAXDEG) + pos] = s;
}
// saves degree, computes dis, resets cursor for next replay
__global__ void k_dis(int n) {
    int i = blockIdx.x * blockDim.x + threadIdx.x;
    if (i >= n) return;
    int d = g_cur[i];
    g_deg[i] = d;
    g_cur[i] = 0;
    g_dis[i] = rsqrtf((float)d + 1.0f);
}

// ---------------- x -> fp16 image ----------------------------------------------
__global__ void k_tohalf(const float* __restrict__ x, __half* __restrict__ xh, int n4) {
    int i = blockIdx.x * blockDim.x + threadIdx.x;
    if (i >= n4) return;
    float4 v = reinterpret_cast<const float4*>(x)[i];
    __half2* o = reinterpret_cast<__half2*>(xh) + 2 * i;
    o[0] = __floats2half2_rn(v.x, v.y);
    o[1] = __floats2half2_rn(v.z, v.w);
}

// ---------------- W split into hi/lo images (row-major, + bias row L1) ---------
__global__ void k_splitW(const float* __restrict__ W1, const float* __restrict__ b1,
                         const float* __restrict__ W2, const float* __restrict__ W3,
                         const float* __restrict__ W4) {
    int idx = blockIdx.x * 256 + threadIdx.x;
    const float* W; const float* bv; int layer, FIN, FOUT, local;
    if (idx < 6240)       { layer = 0; W = W1; bv = b1;      FIN = 64; FOUT = 96; local = idx; }
    else if (idx < 12384) { layer = 1; W = W2; bv = nullptr; FIN = 96; FOUT = 64; local = idx - 6240; }
    else if (idx < 14432) { layer = 2; W = W3; bv = nullptr; FIN = 64; FOUT = 32; local = idx - 12384; }
    else if (idx < 14944) { layer = 3; W = W4; bv = nullptr; FIN = 32; FOUT = 16; local = idx - 14432; }
    else return;
    int krow = local / FOUT;
    int col = local - krow * FOUT;
    float v = (krow < FIN) ? W[krow * FOUT + col] : bv[col];
    __nv_bfloat16 h = __float2bfloat16(v);
    __nv_bfloat16 l = __float2bfloat16(v - __bfloat162float(h));
    g_whi[layer][krow * FOUT + col] = h;
    g_wlo[layer][krow * FOUT + col] = l;
}

// ---------------- gather aggregation (fp16 in, 16B/thread, fp32 out) -----------
// G = F/8 threads per node; each thread owns 8 features -> half the LSU requests
// of the 8B version. 8 fp32 accumulators per thread.
template <int F, bool BIAS>
__global__ void __launch_bounds__(256)
k_agg(const __half* __restrict__ h, const float* __restrict__ bias,
      float* __restrict__ out, int n) {
    constexpr int G = F / 8;
    int tid = blockIdx.x * blockDim.x + threadIdx.x;
    int node = tid / G;
    int v = tid - node * G;
    if (node >= n) return;

    float dn = g_dis[node];
    float d2 = dn * dn;
    float acc[8], a0[8], a1[8], a2[8], a3[8];
    ldh8(h + (size_t)node * F + (v << 3), acc);
#pragma unroll
    for (int q = 0; q < 8; q++) acc[q] *= d2;
    if (BIAS) {
        float4 b0 = *reinterpret_cast<const float4*>(bias + (v << 3));
        float4 b1v = *reinterpret_cast<const float4*>(bias + (v << 3) + 4);
        acc[0] += b0.x; acc[1] += b0.y; acc[2] += b0.z; acc[3] += b0.w;
        acc[4] += b1v.x; acc[5] += b1v.y; acc[6] += b1v.z; acc[7] += b1v.w;
    }
    int deg = g_deg[node];
    if (deg > MAXDEG) deg = MAXDEG;
    const int* slots = g_eslot + ((size_t)node << LOG2_MAXDEG);
    int j = 0;
    for (; j + 4 <= deg; j += 4) {
        int4 s4 = *reinterpret_cast<const int4*>(slots + j);
        float w0 = g_dis[s4.x] * dn;
        float w1 = g_dis[s4.y] * dn;
        float w2 = g_dis[s4.z] * dn;
        float w3 = g_dis[s4.w] * dn;
        ldh8(h + (size_t)s4.x * F + (v << 3), a0);
        ldh8(h + (size_t)s4.y * F + (v << 3), a1);
        ldh8(h + (size_t)s4.z * F + (v << 3), a2);
        ldh8(h + (size_t)s4.w * F + (v << 3), a3);
#pragma unroll
        for (int q = 0; q < 8; q++)
            acc[q] += a0[q] * w0 + a1[q] * w1 + a2[q] * w2 + a3[q] * w3;
    }
    for (; j < deg; j++) {
        int s = slots[j];
        float w = g_dis[s] * dn;
        ldh8(h + (size_t)s * F + (v << 3), a0);
#pragma unroll
        for (int q = 0; q < 8; q++) acc[q] += a0[q] * w;
    }
    float* op = out + (size_t)node * F + (v << 3);
    *reinterpret_cast<float4*>(op)     = make_float4(acc[0], acc[1], acc[2], acc[3]);
    *reinterpret_cast<float4*>(op + 4) = make_float4(acc[4], acc[5], acc[6], acc[7]);
}

// ---------------- WMMA GEMM: split-bf16 x3, fp32 acc ---------------------------
template <int FIN, int FOUT, int KS, bool RELU, bool BIASH, bool OUTH>
__global__ void __launch_bounds__(256)
k_wmma(const float* __restrict__ in, const __nv_bfloat16* __restrict__ wh,
       const __nv_bfloat16* __restrict__ wl, void* __restrict__ outp, int n) {
    constexpr int XLD = KS + 8;
    constexpr int KQ = KS / 4;
    constexpr int KSTEPS = KS / 16;
    constexpr int NT = FOUT / 16;
    extern __shared__ __nv_bfloat16 sm[];
    __nv_bfloat16* Ahi = sm;
    __nv_bfloat16* Alo = Ahi + 128 * XLD;
    __nv_bfloat16* Whi = Alo + 128 * XLD;
    __nv_bfloat16* Wlo = Whi + KS * FOUT;
    const int tid = threadIdx.x;
    const int wid = tid >> 5;
    const int base = blockIdx.x * 128;
    const int rows = (n - base < 128) ? (n - base) : 128;

    {
        const ulonglong2* sh = reinterpret_cast<const ulonglong2*>(wh);
        const ulonglong2* sl = reinterpret_cast<const ulonglong2*>(wl);
        ulonglong2* dh = reinterpret_cast<ulonglong2*>(Whi);
        ulonglong2* dl = reinterpret_cast<ulonglong2*>(Wlo);
        for (int i = tid; i < KS * FOUT / 8; i += 256) { dh[i] = sh[i]; dl[i] = sl[i]; }
    }
    for (int i = tid; i < 128 * KQ; i += 256) {
        int nl = i / KQ;
        int k4 = (i - nl * KQ) << 2;
        ull phi = 0, plo = 0;
        if (k4 < FIN) {
            if (nl < rows) {
                float4 v = *reinterpret_cast<const float4*>(in + (size_t)(base + nl) * FIN + k4);
                if (RELU) {
                    v.x = fmaxf(v.x, 0.f); v.y = fmaxf(v.y, 0.f);
                    v.z = fmaxf(v.z, 0.f); v.w = fmaxf(v.w, 0.f);
                }
                __nv_bfloat16 h0 = __float2bfloat16(v.x), h1 = __float2bfloat16(v.y);
                __nv_bfloat16 h2 = __float2bfloat16(v.z), h3 = __float2bfloat16(v.w);
                __nv_bfloat16 l0 = __float2bfloat16(v.x - __bfloat162float(h0));
                __nv_bfloat16 l1 = __float2bfloat16(v.y - __bfloat162float(h1));
                __nv_bfloat16 l2 = __float2bfloat16(v.z - __bfloat162float(h2));
                __nv_bfloat16 l3 = __float2bfloat16(v.w - __bfloat162float(h3));
                phi = pk4(h0, h1, h2, h3);
                plo = pk4(l0, l1, l2, l3);
            }
        } else if (BIASH && k4 == FIN) {
            phi = 0x3F80ull;                      // bf16 1.0 (ones column)
        }
        *reinterpret_cast<ull*>(Ahi + nl * XLD + k4) = phi;
        *reinterpret_cast<ull*>(Alo + nl * XLD + k4) = plo;
    }
    __syncthreads();

    wmma::fragment<wmma::accumulator, 16, 16, 16, float> acc[NT];
#pragma unroll
    for (int t = 0; t < NT; t++) wmma::fill_fragment(acc[t], 0.0f);

    const __nv_bfloat16* arow = Ahi + (wid * 16) * XLD;
    const __nv_bfloat16* arol = Alo + (wid * 16) * XLD;
#pragma unroll
    for (int ks = 0; ks < KSTEPS; ks++) {
        wmma::fragment<wmma::matrix_a, 16, 16, 16, __nv_bfloat16, wmma::row_major> ah, al;
        wmma::load_matrix_sync(ah, arow + ks * 16, XLD);
        wmma::load_matrix_sync(al, arol + ks * 16, XLD);
#pragma unroll
        for (int t = 0; t < NT; t++) {
            wmma::fragment<wmma::matrix_b, 16, 16, 16, __nv_bfloat16, wmma::row_major> bhf, blf;
            wmma::load_matrix_sync(bhf, Whi + ks * 16 * FOUT + t * 16, FOUT);
            wmma::load_matrix_sync(blf, Wlo + ks * 16 * FOUT + t * 16, FOUT);
            wmma::mma_sync(acc[t], ah, bhf, acc[t]);
            wmma::mma_sync(acc[t], ah, blf, acc[t]);
            wmma::mma_sync(acc[t], al, bhf, acc[t]);
        }
    }

    if (!OUTH) {
        float* orow = reinterpret_cast<float*>(outp) + (size_t)(base + wid * 16) * FOUT;
#pragma unroll
        for (int t = 0; t < NT; t++)
            wmma::store_matrix_sync(orow + t * 16, acc[t], FOUT, wmma::mem_row_major);
    } else {
        __syncthreads();
        float* Ot = reinterpret_cast<float*>(sm);
        float* orow = Ot + (wid * 16) * FOUT;
#pragma unroll
        for (int t = 0; t < NT; t++)
            wmma::store_matrix_sync(orow + t * 16, acc[t], FOUT, wmma::mem_row_major);
        __syncthreads();
        __half2* og = reinterpret_cast<__half2*>(
            reinterpret_cast<__half*>(outp) + (size_t)base * FOUT);
        for (int i = tid; i < 128 * FOUT / 2; i += 256)
            og[i] = __floats2half2_rn(Ot[2 * i], Ot[2 * i + 1]);
    }
}

// ---------------- launch -------------------------------------------------------
extern "C" void kernel_launch(void* const* d_in, const int* in_sizes, int n_in,
                              void* d_out, int out_size) {
    const float* x  = (const float*)d_in[0];
    const int*   ei = (const int*)d_in[1];   // int32
    const float* W1 = (const float*)d_in[2]; const float* b1 = (const float*)d_in[3];
    const float* W2 = (const float*)d_in[4]; const float* b2 = (const float*)d_in[5];
    const float* W3 = (const float*)d_in[6]; const float* b3 = (const float*)d_in[7];
    const float* W4 = (const float*)d_in[8]; const float* b4 = (const float*)d_in[9];
    float* out = (float*)d_out;

    const int n = in_sizes[0] / 64;
    const int e = in_sizes[1] / 2;

    float *bufA, *bufB, *bufH;
    cudaGetSymbolAddress((void**)&bufA, g_bufA);
    cudaGetSymbolAddress((void**)&bufB, g_bufB);
    cudaGetSymbolAddress((void**)&bufH, g_bufH);
    __nv_bfloat16 *whi, *wlo;
    cudaGetSymbolAddress((void**)&whi, g_whi);
    cudaGetSymbolAddress((void**)&wlo, g_wlo);
    __half* xh = (__half*)bufH;
    __half* t2 = (__half*)bufH;
    __half* t3 = (__half*)bufB;
    __half* t4 = (__half*)bufH;

    const int s1 = (2 * 128 * 88  + 2 * 80 * 96) * 2;   // 75776
    const int s2 = (2 * 128 * 104 + 2 * 96 * 64) * 2;   // 77824
    const int s3 = (2 * 128 * 72  + 2 * 64 * 32) * 2;   // 45056
    const int s4 = (2 * 128 * 40  + 2 * 32 * 16) * 2;   // 22528
    cudaFuncSetAttribute(k_wmma<64, 96, 80, false, true,  false>, cudaFuncAttributeMaxDynamicSharedMemorySize, s1);
    cudaFuncSetAttribute(k_wmma<96, 64, 96, true,  false, true>,  cudaFuncAttributeMaxDynamicSharedMemorySize, s2);
    cudaFuncSetAttribute(k_wmma<64, 32, 64, true,  false, true>,  cudaFuncAttributeMaxDynamicSharedMemorySize, s3);
    cudaFuncSetAttribute(k_wmma<32, 16, 32, true,  false, true>,  cudaFuncAttributeMaxDynamicSharedMemorySize, s4);

    const int TB = 256;
    const int nb_n = (n + TB - 1) / TB;
    const int nb_e = (e + TB - 1) / TB;
    const int gblk = (n + 127) / 128;

    // ---- CSR build + W split images + x fp16 image ----
    k_bucketcount<<<nb_e, TB>>>(ei, e, n);
    k_dis<<<nb_n, TB>>>(n);
    k_splitW<<<59, 256>>>(W1, b1, W2, W3, W4);
    k_tohalf<<<(n * 16 + TB - 1) / TB, TB>>>(x, xh, n * 16);

    // ---- layer 1: A1 = A_hat x (fp16 gather, 16B/thread), g1 = A1@W1 + b1 ----
    k_agg<64, false><<<(n * 8 + TB - 1) / TB, TB>>>(xh, nullptr, bufA, n);
    k_wmma<64, 96, 80, false, true, false><<<gblk, 256, s1>>>(bufA, whi + 0 * 8192, wlo + 0 * 8192, bufB, n);

    // ---- layer 2: t2 = relu(g1)@W2 (half out); g2 = A_hat t2 + b2 ----
    k_wmma<96, 64, 96, true, false, true><<<gblk, 256, s2>>>(bufB, whi + 1 * 8192, wlo + 1 * 8192, t2, n);
    k_agg<64, true><<<(n * 8 + TB - 1) / TB, TB>>>(t2, b2, bufA, n);

    // ---- layer 3: t3 = relu(g2)@W3 (half out); g3 = A_hat t3 + b3 ----
    k_wmma<64, 32, 64, true, false, true><<<gblk, 256, s3>>>(bufA, whi + 2 * 8192, wlo + 2 * 8192, t3, n);
    k_agg<32, true><<<(n * 4 + TB - 1) / TB, TB>>>(t3, b3, bufA, n);

    // ---- layer 4: t4 = relu(g3)@W4 (half out); out = A_hat t4 + b4 ----
    k_wmma<32, 16, 32, true, false, true><<<gblk, 256, s4>>>(bufA, whi + 3 * 8192, wlo + 3 * 8192, t4, n);
    k_agg<16, true><<<(n * 2 + TB - 1) / TB, TB>>>(t4, b4, out, n);
}